// round 15
// baseline (speedup 1.0000x reference)
#include <cuda_runtime.h>

#define MEMN 64
#define BN   32
#define LN   64
#define EN   1024
#define HN   1024
#define KS   16         // k-split for skinny GEMMs (partial-array count)
#define KC   (EN / KS)  // 64: k-chunk per block (two 32-wide halves in-block)
#define NV   1152       // padded width of [A^T | TA^T | pad]; uTA at cols 1024..1087
#define NCTA 144        // persistent tail grid (<=148 -> wave-1 co-resident)

#define NWORK   (MEMN * BN + BN)   // 2080 reduce slabs
#define NTRANS  (1024 + 64)        // transpose tiles

// ---------------- scratch (device globals; no allocation allowed) ----------
__device__ __align__(16) float g_X[MEMN * BN * EN];     // 8 MB: X[m][b][e] = sum_l inputs
__device__ __align__(16) float g_qs[BN * EN];           // sum_l questions
__device__ __align__(16) float g_AtX[HN * NV];          // [A^T | TA^T | 0pad], hop-invariant
__device__ __align__(16) float g_upart[KS * BN * HN];   // k-split partials (u-updates)
__device__ __align__(16) float g_vpart[KS * BN * NV];   // k-split partials (v | uTA | pad)
__device__ __align__(16) float g_y[BN * EN];            // y[b][e] = sum_m p_m X[m][b][e]
__device__ __align__(16) float g_opart[BN * HN];        // p @ TC
__device__ unsigned g_bar_count;                        // grid barrier (self-resetting)
__device__ unsigned g_bar_gen;

// ---------------- packed f32x2 helpers (sm_103a FFMA2) ----------------------
__device__ __forceinline__ unsigned long long pack2(float lo, float hi) {
    unsigned long long r;
    asm("mov.b64 %0, {%1, %2};" : "=l"(r)
        : "r"(__float_as_uint(lo)), "r"(__float_as_uint(hi)));
    return r;
}
__device__ __forceinline__ void ffma2(unsigned long long& d,
                                      unsigned long long a, unsigned long long b) {
    asm("fma.rn.f32x2 %0, %1, %2, %0;" : "+l"(d) : "l"(a), "l"(b));
}
__device__ __forceinline__ float2 unpack2(unsigned long long v) {
    unsigned lo, hi;
    asm("mov.b64 {%0, %1}, %2;" : "=r"(lo), "=r"(hi) : "l"(v));
    return make_float2(__uint_as_float(lo), __uint_as_float(hi));
}

// ---------------- software grid barrier (all NCTA CTAs co-resident) ---------
__device__ __forceinline__ void grid_barrier() {
    __syncthreads();
    if (threadIdx.x == 0) {
        volatile unsigned* genp = &g_bar_gen;
        __threadfence();
        unsigned gen = *genp;
        if (atomicAdd(&g_bar_count, 1u) == (unsigned)(gridDim.x - 1)) {
            g_bar_count = 0;
            __threadfence();
            *genp = gen + 1;
        } else {
            while (*genp == gen) { }
        }
    }
    __threadfence();
    __syncthreads();
}

// ---------------- K1: reduce over L (HBM 520MB) + transposes ---------------
// blocks [0,2048): inputs; [2048,2080): questions; [2080,3168): At | TA^T.
__global__ void __launch_bounds__(256) k_reduce(const float* __restrict__ inp,
                                                const float* __restrict__ q,
                                                const float* __restrict__ A,
                                                const float* __restrict__ TA) {
    const int blk = blockIdx.x;
    const int t = threadIdx.x;
    if (blk >= NWORK) {  // transpose tiles
        __shared__ float tile[32][33];
        const int tx = t & 31, ty = t >> 5;  // 32 x 8
        int blk2 = blk - NWORK;
        if (blk2 < 1024) {  // At: g_AtX[h][e] = A[e][h]
            const int h0 = (blk2 & 31) * 32, e0 = (blk2 >> 5) * 32;
#pragma unroll
            for (int j = 0; j < 32; j += 8)
                tile[ty + j][tx] = A[(size_t)(e0 + ty + j) * HN + h0 + tx];
            __syncthreads();
#pragma unroll
            for (int j = 0; j < 32; j += 8)
                g_AtX[(size_t)(h0 + ty + j) * NV + e0 + tx] = tile[tx][ty + j];
        } else {            // TA^T: g_AtX[h][1024+m] = TA[m][h]
            blk2 -= 1024;   // 0..63
            const int h0 = (blk2 >> 1) * 32, m0 = (blk2 & 1) * 32;
#pragma unroll
            for (int j = 0; j < 32; j += 8)
                tile[ty + j][tx] = TA[(size_t)(m0 + ty + j) * HN + h0 + tx];
            __syncthreads();
#pragma unroll
            for (int j = 0; j < 32; j += 8)
                g_AtX[(size_t)(h0 + ty + j) * NV + 1024 + m0 + tx] = tile[tx][ty + j];
        }
        return;
    }
    const float4* src;
    float4* dst;
    if (blk < MEMN * BN) {
        src = (const float4*)(inp + (size_t)blk * LN * EN);
        dst = (float4*)(g_X + (size_t)blk * EN);
    } else {
        const int b = blk - MEMN * BN;
        src = (const float4*)(q + (size_t)b * LN * EN);
        dst = (float4*)(g_qs + (size_t)b * EN);
    }
    float4 a[8];
#pragma unroll
    for (int j = 0; j < 8; ++j) a[j] = make_float4(0.f, 0.f, 0.f, 0.f);
#pragma unroll
    for (int l = 0; l < LN; l += 8) {
#pragma unroll
        for (int j = 0; j < 8; ++j) {
            float4 v = src[(l + j) * (EN / 4) + t];
            a[j].x += v.x; a[j].y += v.y; a[j].z += v.z; a[j].w += v.w;
        }
    }
#pragma unroll
    for (int s = 4; s; s >>= 1)
#pragma unroll
        for (int j = 0; j < s; ++j) {
            a[j].x += a[j + s].x; a[j].y += a[j + s].y;
            a[j].z += a[j + s].z; a[j].w += a[j + s].w;
        }
    dst[t] = a[0];
}

// ---------------- persistent tail: all GEMMs + attend + combines ------------
// Shared buffer layout (union):
//   gemm:   Ss[KC][34] (8704B) then Ws[KC][128] (32768B)
//   attend: vs[1024] | uta[64] | sc[64] | p[64]
__shared__ __align__(16) char sm_raw[8704 + 32768];

// GEMM phase: out[ks] = S[32,KC-chunk] @ W[KC,nw]. tile = cta; nx n-tiles.
// S read via __ldcg (cross-phase); W via normal loads (inputs / prior launch).
__device__ void gemm_phase(const float* S, const float* __restrict__ W,
                           float* out, int nw, int nx) {
    const int cta = blockIdx.x, t = threadIdx.x;
    if (cta >= nx * KS) return;
    float (*Ss)[34] = (float(*)[34])sm_raw;
    float (*Ws)[128] = (float(*)[128])(sm_raw + 8704);
    const int n0 = (cta >> 4) * 128;
    const int ks = cta & 15;
    const int kb = ks * KC;
#pragma unroll
    for (int j = 0; j < 2; ++j) {  // S tile transposed: 32 b x 64 k
        int idx = t + 256 * j;
        int b = idx >> 4, kq = idx & 15;
        float4 v = __ldcg((const float4*)(S + (size_t)b * EN + kb + 4 * kq));
        Ss[4 * kq + 0][b] = v.x;
        Ss[4 * kq + 1][b] = v.y;
        Ss[4 * kq + 2][b] = v.z;
        Ss[4 * kq + 3][b] = v.w;
    }
#pragma unroll
    for (int j = 0; j < 8; ++j) {  // W tile: 64 x 128
        int idx = t + 256 * j;
        int k = idx >> 5, qq = idx & 31;
        *(float4*)&Ws[k][4 * qq] = *(const float4*)(W + (size_t)(kb + k) * nw + n0 + 4 * qq);
    }
    __syncthreads();
    const int half = t >> 7, t1 = t & 127;
    const int tx = t1 & 31, ty = t1 >> 5;
    const int koff = half * 32;
    unsigned long long acc[4][4];
#pragma unroll
    for (int i = 0; i < 4; ++i)
#pragma unroll
        for (int j = 0; j < 4; ++j) acc[i][j] = 0ull;
#pragma unroll 4
    for (int kk = 0; kk < 32; ++kk) {
        const int k = koff + kk;
        float4 w = *(const float4*)&Ws[k][4 * tx];
        unsigned long long w0 = pack2(w.x, w.x), w1 = pack2(w.y, w.y);
        unsigned long long w2 = pack2(w.z, w.z), w3 = pack2(w.w, w.w);
        const float* srow = &Ss[k][8 * ty];
        unsigned long long s0 = *(const unsigned long long*)(srow + 0);
        unsigned long long s1 = *(const unsigned long long*)(srow + 2);
        unsigned long long s2 = *(const unsigned long long*)(srow + 4);
        unsigned long long s3 = *(const unsigned long long*)(srow + 6);
        ffma2(acc[0][0], s0, w0); ffma2(acc[0][1], s0, w1);
        ffma2(acc[0][2], s0, w2); ffma2(acc[0][3], s0, w3);
        ffma2(acc[1][0], s1, w0); ffma2(acc[1][1], s1, w1);
        ffma2(acc[1][2], s1, w2); ffma2(acc[1][3], s1, w3);
        ffma2(acc[2][0], s2, w0); ffma2(acc[2][1], s2, w1);
        ffma2(acc[2][2], s2, w2); ffma2(acc[2][3], s2, w3);
        ffma2(acc[3][0], s3, w0); ffma2(acc[3][1], s3, w1);
        ffma2(acc[3][2], s3, w2); ffma2(acc[3][3], s3, w3);
    }
    __syncthreads();
    float* buf = &Ws[0][0];
    if (half == 1) {
#pragma unroll
        for (int i = 0; i < 4; ++i) {
            float2 c0 = unpack2(acc[i][0]), c1 = unpack2(acc[i][1]);
            float2 c2 = unpack2(acc[i][2]), c3 = unpack2(acc[i][3]);
            *(float4*)&buf[(8 * ty + 2 * i) * 128 + 4 * tx] =
                make_float4(c0.x, c1.x, c2.x, c3.x);
            *(float4*)&buf[(8 * ty + 2 * i + 1) * 128 + 4 * tx] =
                make_float4(c0.y, c1.y, c2.y, c3.y);
        }
    }
    __syncthreads();
    if (half == 0) {
#pragma unroll
        for (int i = 0; i < 4; ++i) {
            float2 c0 = unpack2(acc[i][0]), c1 = unpack2(acc[i][1]);
            float2 c2 = unpack2(acc[i][2]), c3 = unpack2(acc[i][3]);
            float4 r0 = *(const float4*)&buf[(8 * ty + 2 * i) * 128 + 4 * tx];
            float4 r1 = *(const float4*)&buf[(8 * ty + 2 * i + 1) * 128 + 4 * tx];
            float4 o0 = make_float4(c0.x + r0.x, c1.x + r0.y, c2.x + r0.z, c3.x + r0.w);
            float4 o1 = make_float4(c0.y + r1.x, c1.y + r1.y, c2.y + r1.z, c3.y + r1.w);
            float* op = out + ((size_t)ks * BN + 8 * ty + 2 * i) * nw + n0 + 4 * tx;
            *(float4*)op = o0;
            *(float4*)(op + nw) = o1;
        }
    }
}

// Attend phase: per (b, e-chunk) CTA: scores -> softmax -> y, opart.
__device__ void attend_phase(const float* __restrict__ TC) {
    const int cta = blockIdx.x, t = threadIdx.x;
    if (cta >= BN * 4) return;
    const int b = cta >> 2, ec = cta & 3;
    float* vs = (float*)sm_raw;          // [1024]
    float* uta = vs + EN;                // [64]
    float* sc = uta + MEMN;              // [64]
    float* p = sc + MEMN;                // [64]
    {
        float4 s = make_float4(0.f, 0.f, 0.f, 0.f);
#pragma unroll
        for (int k = 0; k < KS; ++k) {
            float4 v = __ldcg((const float4*)(g_vpart + ((size_t)k * BN + b) * NV + 4 * t));
            s.x += v.x; s.y += v.y; s.z += v.z; s.w += v.w;
        }
        *(float4*)&vs[4 * t] = s;
        if (t < MEMN) {
            float su = 0.f;
#pragma unroll
            for (int k = 0; k < KS; ++k)
                su += __ldcg(g_vpart + ((size_t)k * BN + b) * NV + 1024 + t);
            uta[t] = su;
        }
    }
    __syncthreads();
    const int warp = t >> 5, lane = t & 31;
#pragma unroll
    for (int i = 0; i < 8; ++i) {
        const int m = i * 8 + warp;
        const float* xr = g_X + ((size_t)m * BN + b) * EN;
        float s = 0.f;
#pragma unroll
        for (int it = 0; it < 8; ++it) {
            int e = it * 128 + lane * 4;
            float4 x = *(const float4*)(xr + e);
            s += vs[e] * x.x + vs[e + 1] * x.y + vs[e + 2] * x.z + vs[e + 3] * x.w;
        }
#pragma unroll
        for (int o = 16; o; o >>= 1) s += __shfl_xor_sync(0xffffffffu, s, o);
        if (lane == 0) sc[m] = s + uta[m];
    }
    __syncthreads();
    if (warp == 0) {
        float s0 = sc[lane], s1 = sc[lane + 32];
        float mx = fmaxf(s0, s1);
#pragma unroll
        for (int o = 16; o; o >>= 1) mx = fmaxf(mx, __shfl_xor_sync(0xffffffffu, mx, o));
        float e0 = __expf(s0 - mx), e1 = __expf(s1 - mx);
        float sum = e0 + e1;
#pragma unroll
        for (int o = 16; o; o >>= 1) sum += __shfl_xor_sync(0xffffffffu, sum, o);
        float inv = 1.f / sum;
        p[lane] = e0 * inv;
        p[lane + 32] = e1 * inv;
    }
    __syncthreads();
    const int e0 = ec * 256;
    if (t < 128) {
        const int isop = t >> 6, sl = t & 63;
        const float* base = isop ? (TC + e0 + 4 * sl)
                                 : (g_X + (size_t)b * EN + e0 + 4 * sl);
        const size_t stride = isop ? (size_t)HN : (size_t)BN * EN;
        float4 acc = make_float4(0.f, 0.f, 0.f, 0.f);
#pragma unroll 8
        for (int m = 0; m < MEMN; ++m) {
            float pm = p[m];
            float4 v = *(const float4*)(base + m * stride);
            acc.x += pm * v.x; acc.y += pm * v.y; acc.z += pm * v.z; acc.w += pm * v.w;
        }
        float* dst = isop ? (g_opart + (size_t)b * HN + e0 + 4 * sl)
                          : (g_y + (size_t)b * EN + e0 + 4 * sl);
        *(float4*)dst = acc;
    }
}

// Combine phase: u (= | +=) sum_ks upart (+ opart). 8192 float4s.
__device__ void combine_phase(float* u, int acc) {
    const int i = blockIdx.x * 256 + threadIdx.x;
    if (i >= 8192) return;
    float4 s = make_float4(0.f, 0.f, 0.f, 0.f);
#pragma unroll
    for (int k = 0; k < KS; ++k) {
        float4 v = __ldcg((const float4*)(g_upart + (size_t)k * BN * HN + 4 * i));
        s.x += v.x; s.y += v.y; s.z += v.z; s.w += v.w;
    }
    if (acc) {
        float4 u0 = __ldcg((const float4*)(u + 4 * i));
        float4 o = __ldcg((const float4*)(g_opart + 4 * i));
        s.x += u0.x + o.x; s.y += u0.y + o.y; s.z += u0.z + o.z; s.w += u0.w + o.w;
    }
    *(float4*)(u + 4 * i) = s;
}

__global__ void __launch_bounds__(256) k_tail(const float* __restrict__ C,
                                              const float* __restrict__ Bmat,
                                              const float* __restrict__ TC,
                                              float* __restrict__ u) {
    // u = qs @ Bmat
    gemm_phase(g_qs, Bmat, g_upart, HN, 8);
    grid_barrier();
    combine_phase(u, 0);
    grid_barrier();
    for (int hop = 0; hop < 3; ++hop) {
        gemm_phase(u, g_AtX, g_vpart, NV, 9);     // [v | uTA] = u @ [A^T|TA^T]
        grid_barrier();
        attend_phase(TC);                          // softmax -> y, opart
        grid_barrier();
        gemm_phase(g_y, C, g_upart, HN, 8);        // upart = y @ C
        grid_barrier();
        combine_phase(u, 1);                       // u += sum upart + opart
        if (hop < 2) grid_barrier();
    }
}

// ---------------- launch -----------------------------------------------------
extern "C" void kernel_launch(void* const* d_in, const int* in_sizes, int n_in,
                              void* d_out, int out_size) {
    const float* inputs    = (const float*)d_in[0];  // [64,32,64,1024]
    const float* questions = (const float*)d_in[1];  // [32,64,1024]
    const float* A         = (const float*)d_in[2];  // [1024,1024]
    const float* C         = (const float*)d_in[3];  // [1024,1024]
    const float* Bmat      = (const float*)d_in[4];  // [1024,1024]
    const float* TA        = (const float*)d_in[5];  // [64,1024]
    const float* TC        = (const float*)d_in[6];  // [64,1024]
    float* u = (float*)d_out;                        // [32,1024]

    // X = sum_l inputs ; qs = sum_l questions ; AtX = [A^T | TA^T]
    k_reduce<<<NWORK + NTRANS, 256>>>(inputs, questions, A, TA);
    // entire multi-hop tail in one persistent kernel
    k_tail<<<NCTA, 256>>>(C, Bmat, TC, u);
}

// round 17
// speedup vs baseline: 1.3787x; 1.3787x over previous
#include <cuda_runtime.h>

#define MEMN 64
#define BN   32
#define LN   64
#define EN   1024
#define HN   1024
#define KS   16         // k-split for skinny GEMMs (partial-array count)
#define KC   (EN / KS)  // 64: k-chunk per block (two 32-wide halves in-block)
#define NV   1152       // padded width of [A^T | TA^T | pad]; uTA at cols 1024..1087

#define NWORK   (MEMN * BN + BN)   // 2080 reduce slabs
#define NTRANS  (1024 + 64)        // transpose tiles
#define PFBASE  (NWORK + NTRANS)   // 3168: prefetch blocks start here
#define NPF     65                 // 16 Bmat + 16 C + 32 X + 1 TC

// ---------------- scratch (device globals; no allocation allowed) ----------
__device__ __align__(16) float g_X[MEMN * BN * EN];     // 8 MB: X[m][b][e] = sum_l inputs
__device__ __align__(16) float g_qs[BN * EN];           // sum_l questions
__device__ __align__(16) float g_AtX[HN * NV];          // [A^T | TA^T | 0pad], hop-invariant
__device__ __align__(16) float g_upart[KS * BN * HN];   // k-split partials (u-updates)
__device__ __align__(16) float g_vpart[KS * BN * NV];   // k-split partials (v | uTA | pad)
__device__ __align__(16) float g_y[BN * EN];            // y[b][e] = sum_m p_m X[m][b][e]
__device__ __align__(16) float g_opart[BN * HN];        // p @ TC
__device__ float g_pf[NPF * 8];                         // prefetch sink (never read)

// ---------------- packed f32x2 helpers (sm_103a FFMA2) ----------------------
__device__ __forceinline__ unsigned long long pack2(float lo, float hi) {
    unsigned long long r;
    asm("mov.b64 %0, {%1, %2};" : "=l"(r)
        : "r"(__float_as_uint(lo)), "r"(__float_as_uint(hi)));
    return r;
}
__device__ __forceinline__ void ffma2(unsigned long long& d,
                                      unsigned long long a, unsigned long long b) {
    asm("fma.rn.f32x2 %0, %1, %2, %0;" : "+l"(d) : "l"(a), "l"(b));
}
__device__ __forceinline__ float2 unpack2(unsigned long long v) {
    unsigned lo, hi;
    asm("mov.b64 {%0, %1}, %2;" : "=r"(lo), "=r"(hi) : "l"(v));
    return make_float2(__uint_as_float(lo), __uint_as_float(hi));
}

// ---------------- K1: reduce over L (HBM 520MB) + transposes + L2 prefetch -
// blocks [0,2048): inputs; [2048,2080): questions; [2080,3168): At|TA^T;
// [3168,3233): L2 prefetch of Bmat, C, g_X, TC. The 512MB stream is read with
// __ldcs (evict-first) so it recycles its own L2 lines instead of flushing the
// tail's ~25MB working set (weights stay warm ACROSS graph replays).
__global__ void __launch_bounds__(256) k_reduce(const float* __restrict__ inp,
                                                const float* __restrict__ q,
                                                const float* __restrict__ A,
                                                const float* __restrict__ TA,
                                                const float* __restrict__ Bm,
                                                const float* __restrict__ Cm,
                                                const float* __restrict__ TC) {
    const int blk = blockIdx.x;
    const int t = threadIdx.x;
    if (blk >= PFBASE) {  // L2 prefetch blocks: 256KB each
        const int pb = blk - PFBASE;
        const float* src;
        if (pb < 16)      src = Bm + (size_t)pb * 65536;
        else if (pb < 32) src = Cm + (size_t)(pb - 16) * 65536;
        else if (pb < 64) src = g_X + (size_t)(pb - 32) * 65536;
        else              src = TC;                      // 256KB = whole TC
        const float4* s4 = (const float4*)src;
        float acc = 0.f;
#pragma unroll 16
        for (int j = 0; j < 64; ++j) {
            float4 v = s4[t + 256 * j];
            acc += v.x + v.y + v.z + v.w;
        }
#pragma unroll
        for (int o = 16; o; o >>= 1) acc += __shfl_xor_sync(0xffffffffu, acc, o);
        if ((t & 31) == 0) g_pf[pb * 8 + (t >> 5)] = acc;  // keep loads live
        return;
    }
    if (blk >= NWORK) {  // transpose tiles
        __shared__ float tile[32][33];
        const int tx = t & 31, ty = t >> 5;  // 32 x 8
        int blk2 = blk - NWORK;
        if (blk2 < 1024) {  // At: g_AtX[h][e] = A[e][h]
            const int h0 = (blk2 & 31) * 32, e0 = (blk2 >> 5) * 32;
#pragma unroll
            for (int j = 0; j < 32; j += 8)
                tile[ty + j][tx] = A[(size_t)(e0 + ty + j) * HN + h0 + tx];
            __syncthreads();
#pragma unroll
            for (int j = 0; j < 32; j += 8)
                g_AtX[(size_t)(h0 + ty + j) * NV + e0 + tx] = tile[tx][ty + j];
        } else {            // TA^T: g_AtX[h][1024+m] = TA[m][h]
            blk2 -= 1024;   // 0..63
            const int h0 = (blk2 >> 1) * 32, m0 = (blk2 & 1) * 32;
#pragma unroll
            for (int j = 0; j < 32; j += 8)
                tile[ty + j][tx] = TA[(size_t)(m0 + ty + j) * HN + h0 + tx];
            __syncthreads();
#pragma unroll
            for (int j = 0; j < 32; j += 8)
                g_AtX[(size_t)(h0 + ty + j) * NV + 1024 + m0 + tx] = tile[tx][ty + j];
        }
        return;
    }
    const float4* src;
    float4* dst;
    if (blk < MEMN * BN) {
        src = (const float4*)(inp + (size_t)blk * LN * EN);
        dst = (float4*)(g_X + (size_t)blk * EN);
    } else {
        const int b = blk - MEMN * BN;
        src = (const float4*)(q + (size_t)b * LN * EN);
        dst = (float4*)(g_qs + (size_t)b * EN);
    }
    float4 a[8];
#pragma unroll
    for (int j = 0; j < 8; ++j) a[j] = make_float4(0.f, 0.f, 0.f, 0.f);
#pragma unroll
    for (int l = 0; l < LN; l += 8) {
#pragma unroll
        for (int j = 0; j < 8; ++j) {
            float4 v = __ldcs(&src[(l + j) * (EN / 4) + t]);   // evict-first stream
            a[j].x += v.x; a[j].y += v.y; a[j].z += v.z; a[j].w += v.w;
        }
    }
#pragma unroll
    for (int s = 4; s; s >>= 1)
#pragma unroll
        for (int j = 0; j < s; ++j) {
            a[j].x += a[j + s].x; a[j].y += a[j + s].y;
            a[j].z += a[j + s].z; a[j].w += a[j + s].w;
        }
    dst[t] = a[0];
}

// ---------------- skinny GEMM NN: out[ks] = S[32,KC] @ W[KC,nw] ------------
// grid (nw/128, KS), 256 threads = 2 k-halves of 4 warps. Each half: 8b x 4n
// per thread, accumulators packed over b-pairs (FFMA2). In-block k-reduction.
__global__ void __launch_bounds__(256) k_gemm(const float* __restrict__ S,
                                              const float* __restrict__ W,
                                              float* __restrict__ out, int nw) {
    __shared__ float Ss[KC][34];    // [k][b] transposed; rows 136B (8B-aligned pairs)
    __shared__ float Ws[KC][128];   // [k][n] 32KB; reused as reduction buffer
    const int n0 = blockIdx.x * 128;
    const int kb = blockIdx.y * KC;
    const int t = threadIdx.x;
    // S tile (transposed): 32 b x 64 k, 512 f4, 2 per thread
#pragma unroll
    for (int j = 0; j < 2; ++j) {
        int idx = t + 256 * j;
        int b = idx >> 4, kq = idx & 15;
        float4 v = *(const float4*)(S + (size_t)b * EN + kb + 4 * kq);
        Ss[4 * kq + 0][b] = v.x;
        Ss[4 * kq + 1][b] = v.y;
        Ss[4 * kq + 2][b] = v.z;
        Ss[4 * kq + 3][b] = v.w;
    }
    // W tile: 64 x 128, 2048 f4, 8 per thread
#pragma unroll
    for (int j = 0; j < 8; ++j) {
        int idx = t + 256 * j;
        int k = idx >> 5, qq = idx & 31;
        *(float4*)&Ws[k][4 * qq] = *(const float4*)(W + (size_t)(kb + k) * nw + n0 + 4 * qq);
    }
    __syncthreads();
    const int half = t >> 7, t1 = t & 127;
    const int tx = t1 & 31, ty = t1 >> 5;   // tx: n-group(32), ty: b-group(4 rows of 8)
    const int koff = half * 32;
    unsigned long long acc[4][4];           // [b-pair i][n j]
#pragma unroll
    for (int i = 0; i < 4; ++i)
#pragma unroll
        for (int j = 0; j < 4; ++j) acc[i][j] = 0ull;
#pragma unroll 4
    for (int kk = 0; kk < 32; ++kk) {
        const int k = koff + kk;
        float4 w = *(const float4*)&Ws[k][4 * tx];
        unsigned long long w0 = pack2(w.x, w.x), w1 = pack2(w.y, w.y);
        unsigned long long w2 = pack2(w.z, w.z), w3 = pack2(w.w, w.w);
        const float* srow = &Ss[k][8 * ty];
        unsigned long long s0 = *(const unsigned long long*)(srow + 0);
        unsigned long long s1 = *(const unsigned long long*)(srow + 2);
        unsigned long long s2 = *(const unsigned long long*)(srow + 4);
        unsigned long long s3 = *(const unsigned long long*)(srow + 6);
        ffma2(acc[0][0], s0, w0); ffma2(acc[0][1], s0, w1);
        ffma2(acc[0][2], s0, w2); ffma2(acc[0][3], s0, w3);
        ffma2(acc[1][0], s1, w0); ffma2(acc[1][1], s1, w1);
        ffma2(acc[1][2], s1, w2); ffma2(acc[1][3], s1, w3);
        ffma2(acc[2][0], s2, w0); ffma2(acc[2][1], s2, w1);
        ffma2(acc[2][2], s2, w2); ffma2(acc[2][3], s2, w3);
        ffma2(acc[3][0], s3, w0); ffma2(acc[3][1], s3, w1);
        ffma2(acc[3][2], s3, w2); ffma2(acc[3][3], s3, w3);
    }
    // In-block reduction of the two k-halves (reuse Ws as [32][128] buffer).
    __syncthreads();
    float* buf = &Ws[0][0];
    if (half == 1) {
#pragma unroll
        for (int i = 0; i < 4; ++i) {
            float2 c0 = unpack2(acc[i][0]), c1 = unpack2(acc[i][1]);
            float2 c2 = unpack2(acc[i][2]), c3 = unpack2(acc[i][3]);
            *(float4*)&buf[(8 * ty + 2 * i) * 128 + 4 * tx] =
                make_float4(c0.x, c1.x, c2.x, c3.x);
            *(float4*)&buf[(8 * ty + 2 * i + 1) * 128 + 4 * tx] =
                make_float4(c0.y, c1.y, c2.y, c3.y);
        }
    }
    __syncthreads();
    if (half == 0) {
#pragma unroll
        for (int i = 0; i < 4; ++i) {
            float2 c0 = unpack2(acc[i][0]), c1 = unpack2(acc[i][1]);
            float2 c2 = unpack2(acc[i][2]), c3 = unpack2(acc[i][3]);
            float4 r0 = *(const float4*)&buf[(8 * ty + 2 * i) * 128 + 4 * tx];
            float4 r1 = *(const float4*)&buf[(8 * ty + 2 * i + 1) * 128 + 4 * tx];
            float4 o0 = make_float4(c0.x + r0.x, c1.x + r0.y, c2.x + r0.z, c3.x + r0.w);
            float4 o1 = make_float4(c0.y + r1.x, c1.y + r1.y, c2.y + r1.z, c3.y + r1.w);
            float* op = out + ((size_t)blockIdx.y * BN + 8 * ty + 2 * i) * nw + n0 + 4 * tx;
            *(float4*)op = o0;
            *(float4*)(op + nw) = o1;
        }
    }
}

// ---------------- K2: fused attend: scores -> softmax -> y, opart ----------
// grid (32 b, 4 e-chunks of 256), 256 threads. scores recomputed per chunk.
__global__ void __launch_bounds__(256) k_attend(const float* __restrict__ TC) {
    __shared__ float vs[EN];
    __shared__ float uta[MEMN];
    __shared__ float sc[MEMN];
    __shared__ float p[MEMN];
    const int b = blockIdx.x, t = threadIdx.x;
    // Phase 1: vs = sum_ks vpart[ks][b][0:1024]; uta[m] = sum_ks vpart[ks][b][1024+m]
    {
        float4 s = make_float4(0.f, 0.f, 0.f, 0.f);
#pragma unroll
        for (int k = 0; k < KS; ++k) {
            float4 v = *(const float4*)(g_vpart + ((size_t)k * BN + b) * NV + 4 * t);
            s.x += v.x; s.y += v.y; s.z += v.z; s.w += v.w;
        }
        *(float4*)&vs[4 * t] = s;
        if (t < MEMN) {
            float su = 0.f;
#pragma unroll
            for (int k = 0; k < KS; ++k)
                su += g_vpart[((size_t)k * BN + b) * NV + 1024 + t];
            uta[t] = su;
        }
    }
    __syncthreads();
    // Phase 2: scores. 8 warps x 8 m each.
    const int warp = t >> 5, lane = t & 31;
#pragma unroll
    for (int i = 0; i < 8; ++i) {
        const int m = i * 8 + warp;
        const float* xr = g_X + ((size_t)m * BN + b) * EN;
        float s = 0.f;
#pragma unroll
        for (int it = 0; it < 8; ++it) {
            int e = it * 128 + lane * 4;
            float4 x = *(const float4*)(xr + e);
            s += vs[e] * x.x + vs[e + 1] * x.y + vs[e + 2] * x.z + vs[e + 3] * x.w;
        }
#pragma unroll
        for (int o = 16; o; o >>= 1) s += __shfl_xor_sync(0xffffffffu, s, o);
        if (lane == 0) sc[m] = s + uta[m];
    }
    __syncthreads();
    // Phase 3: softmax (warp 0)
    if (warp == 0) {
        float s0 = sc[lane], s1 = sc[lane + 32];
        float mx = fmaxf(s0, s1);
#pragma unroll
        for (int o = 16; o; o >>= 1) mx = fmaxf(mx, __shfl_xor_sync(0xffffffffu, mx, o));
        float e0 = __expf(s0 - mx), e1 = __expf(s1 - mx);
        float sum = e0 + e1;
#pragma unroll
        for (int o = 16; o; o >>= 1) sum += __shfl_xor_sync(0xffffffffu, sum, o);
        float inv = 1.f / sum;
        p[lane] = e0 * inv;
        p[lane + 32] = e1 * inv;
    }
    __syncthreads();
    // Phase 4: this chunk's y and opart (threads 0..127: 64 f4 y + 64 f4 op)
    const int e0 = blockIdx.y * 256;
    if (t < 128) {
        const int isop = t >> 6, sl = t & 63;
        const float* base = isop ? (TC + (size_t)0 * HN + e0 + 4 * sl)
                                 : (g_X + (size_t)b * EN + e0 + 4 * sl);
        const size_t stride = isop ? (size_t)HN : (size_t)BN * EN;
        float4 acc = make_float4(0.f, 0.f, 0.f, 0.f);
#pragma unroll 8
        for (int m = 0; m < MEMN; ++m) {
            float pm = p[m];
            float4 v = *(const float4*)(base + m * stride);
            acc.x += pm * v.x; acc.y += pm * v.y; acc.z += pm * v.z; acc.w += pm * v.w;
        }
        float* dst = isop ? (g_opart + (size_t)b * HN + e0 + 4 * sl)
                          : (g_y + (size_t)b * EN + e0 + 4 * sl);
        *(float4*)dst = acc;
    }
}

// ---------------- combine: u (= | +=) sum_ks upart (+ opart) ---------------
__global__ void __launch_bounds__(64) k_combine(float* __restrict__ U, int acc) {
    const int i = blockIdx.x * 64 + threadIdx.x;  // 8192 float4s
    float4 s = make_float4(0.f, 0.f, 0.f, 0.f);
#pragma unroll
    for (int k = 0; k < KS; ++k) {
        float4 v = *(const float4*)(g_upart + (size_t)k * BN * HN + 4 * i);
        s.x += v.x; s.y += v.y; s.z += v.z; s.w += v.w;
    }
    if (acc) {
        float4 u0 = *(const float4*)(U + 4 * i);
        float4 o = *(const float4*)(g_opart + 4 * i);
        s.x += u0.x + o.x; s.y += u0.y + o.y; s.z += u0.z + o.z; s.w += u0.w + o.w;
    }
    *(float4*)(U + 4 * i) = s;
}

// ---------------- launch -----------------------------------------------------
extern "C" void kernel_launch(void* const* d_in, const int* in_sizes, int n_in,
                              void* d_out, int out_size) {
    const float* inputs    = (const float*)d_in[0];  // [64,32,64,1024]
    const float* questions = (const float*)d_in[1];  // [32,64,1024]
    const float* A         = (const float*)d_in[2];  // [1024,1024]
    const float* C         = (const float*)d_in[3];  // [1024,1024]
    const float* Bmat      = (const float*)d_in[4];  // [1024,1024]
    const float* TA        = (const float*)d_in[5];  // [64,1024]
    const float* TC        = (const float*)d_in[6];  // [64,1024]
    float* u = (float*)d_out;                        // [32,1024]

    float* g_qs_p;   cudaGetSymbolAddress((void**)&g_qs_p, g_qs);
    float* g_AtX_p;  cudaGetSymbolAddress((void**)&g_AtX_p, g_AtX);
    float* g_y_p;    cudaGetSymbolAddress((void**)&g_y_p, g_y);
    float* g_up_p;   cudaGetSymbolAddress((void**)&g_up_p, g_upart);
    float* g_vp_p;   cudaGetSymbolAddress((void**)&g_vp_p, g_vpart);

    // X = sum_l inputs ; qs = sum_l questions ; AtX = [A^T | TA^T] ; L2 prefetch
    k_reduce<<<PFBASE + NPF, 256>>>(inputs, questions, A, TA, Bmat, C, TC);
    // u = qs @ Bmat
    k_gemm<<<dim3(8, KS), 256>>>(g_qs_p, Bmat, g_up_p, HN);
    k_combine<<<128, 64>>>(u, 0);

    for (int hop = 0; hop < 3; ++hop) {
        // [v | uTA] = u @ [A^T | TA^T]
        k_gemm<<<dim3(9, KS), 256>>>(u, g_AtX_p, g_vp_p, NV);
        // scores -> softmax -> y = p.X, opart = p@TC (fused)
        k_attend<<<dim3(BN, 4), 256>>>(TC);
        // upart = y @ C
        k_gemm<<<dim3(8, KS), 256>>>(g_y_p, C, g_up_p, HN);
        // u += sum upart + opart
        k_combine<<<128, 64>>>(u, 1);
    }
}